// round 15
// baseline (speedup 1.0000x reference)
#include <cuda_runtime.h>
#include <cuda_fp16.h>
#include <cstdint>

// Problem constants
#define MM   32
#define BB   1000
#define H1   512
#define H2   2048
#define DD   3072

#define X1_ROWS 2048   // interleaved: row 2b = h_b, row 2b+1 = t_b (b<1024, pads 0)
#define T2_ROWS 1024
#define NPART   512

// ---------------------------------------------------------------------------
// Static device scratch (all fp16).
// ---------------------------------------------------------------------------
__device__ __align__(16) __half g_X1h[X1_ROWS * H1];    // 2 MB
__device__ __align__(16) __half g_W2th[H2 * H1];        // [N=2048,K=512]  2 MB
__device__ __align__(16) __half g_W3th[DD * H2];        // [N=3072,K=2048] 12 MB
__device__ __align__(16) __half g_T2h[T2_ROWS * H2];    // 4 MB
__device__ float g_part[NPART];

__device__ __forceinline__ uint32_t smem_u32(const void* p) {
    uint32_t a;
    asm("{ .reg .u64 t; cvta.to.shared.u64 t, %1; cvt.u32.u64 %0, t; }"
        : "=r"(a) : "l"(p));
    return a;
}

// ---------------------------------------------------------------------------
// K1: layer-1 forward + tangent -> interleaved fp16 rows (2b = h, 2b+1 = t).
// ---------------------------------------------------------------------------
__global__ void k_layer1(const float* __restrict__ c0,
                         const float* __restrict__ c1,
                         const float* __restrict__ interior,
                         const float* __restrict__ W1,
                         const float* __restrict__ b1) {
    int b = blockIdx.x;            // 0..1023
    if (b >= BB) {
        const __half z = __float2half(0.0f);
        for (int k = threadIdx.x; k < H1; k += blockDim.x) {
            g_X1h[(2 * b) * H1 + k]     = z;
            g_X1h[(2 * b + 1) * H1 + k] = z;
        }
        return;
    }
    __shared__ float zs[MM], ds[MM];
    if (threadIdx.x < MM) {
        int m = threadIdx.x;
        float zb = (b == 0)    ? c0[m] : interior[(b - 1) * MM + m];
        float cn = (b == BB-1) ? c1[m] : interior[b * MM + m];
        zs[m] = zb;
        ds[m] = cn - zb;
    }
    __syncthreads();
    for (int k = threadIdx.x; k < H1; k += blockDim.x) {
        float a = b1[k];
        float g = 0.0f;
        #pragma unroll
        for (int m = 0; m < MM; ++m) {
            float w = W1[m * H1 + k];
            a = fmaf(zs[m], w, a);
            g = fmaf(ds[m], w, g);
        }
        float h = fmaxf(a, 0.0f);
        float t = (a > 0.0f) ? g : 0.0f;
        g_X1h[(2 * b) * H1 + k]     = __float2half_rn(h);
        g_X1h[(2 * b + 1) * H1 + k] = __float2half_rn(t);
    }
}

// ---------------------------------------------------------------------------
// Transpose -> fp16:  W[K,N] fp32 -> T[N,K] fp16.  64-wide K tiles, half2
// stores (128 B/warp coalesced writes).  Requires K%64==0, N%32==0.
// ---------------------------------------------------------------------------
__global__ void k_transpose_half(const float* __restrict__ W,
                                 __half* __restrict__ T,
                                 int K, int N) {
    __shared__ float tile[64][33];
    int n0 = blockIdx.x * 32;
    int k0 = blockIdx.y * 64;
    int tx = threadIdx.x, ty = threadIdx.y;   // (32, 8)
    #pragma unroll
    for (int r = ty; r < 64; r += 8)
        tile[r][tx] = W[(size_t)(k0 + r) * N + n0 + tx];
    __syncthreads();
    #pragma unroll
    for (int n = ty; n < 32; n += 8) {
        __half2 v = __halves2half2(__float2half_rn(tile[2 * tx][n]),
                                   __float2half_rn(tile[2 * tx + 1][n]));
        *(__half2*)&T[(size_t)(n0 + n) * K + k0 + 2 * tx] = v;
    }
}

// ---------------------------------------------------------------------------
// Single-pass fp16 mma.sync GEMM, BK=64, multi-stage cp.async.
// Template: MODE 0 = gate epilogue; MODE 1 = sqsum epilogue.
//           BNT = N tile width; NST = pipeline stages.
// CTA tile 128 x BNT, 8 warps, warp tile 32 x (BNT/2).
// ---------------------------------------------------------------------------
#define BM 128
#define BK 64
#define LDSR 72          // 16-bit elems/row (144 B): stride 36 words -> 4r mod 32,
                         // 8 ldmatrix rows' 16B chunks bank-disjoint
#define TILE_A (BM * LDSR * 2)      // 18432 bytes per A stage

#define LDSM_X4(d, addr)                                                     \
    asm volatile("ldmatrix.sync.aligned.m8n8.x4.shared.b16 {%0,%1,%2,%3}, [%4];" \
                 : "=r"((d)[0]), "=r"((d)[1]), "=r"((d)[2]), "=r"((d)[3])    \
                 : "r"(addr))

#define MMA_FP16(ac, av, r0, r1)                                             \
    asm volatile(                                                            \
        "mma.sync.aligned.m16n8k16.row.col.f32.f16.f16.f32 "                 \
        "{%0,%1,%2,%3}, {%4,%5,%6,%7}, {%8,%9}, {%0,%1,%2,%3};"              \
        : "+f"((ac)[0]), "+f"((ac)[1]), "+f"((ac)[2]), "+f"((ac)[3])         \
        : "r"((av)[0]), "r"((av)[1]), "r"((av)[2]), "r"((av)[3]),            \
          "r"(r0), "r"(r1))

template <int MODE, int BNT, int NST>
__global__ void __launch_bounds__(256, 2)
k_mma_gemm(const uint16_t* __restrict__ A, const uint16_t* __restrict__ B,
           const float* __restrict__ aux,   // MODE0: b2;  MODE1: unused
           int K, int KT) {                 // KT = K/BK
    constexpr int TILE_BB = BNT * LDSR * 2;       // B stage bytes
    constexpr int G  = BNT / 32;                  // ldsm.x4 B groups per warp
    constexpr int NF = BNT / 16;                  // n8 acc frags per warp
    constexpr int CPB = (BNT == 128) ? 4 : 2;     // B chunks per thread

    extern __shared__ char sm[];
    const uint32_t aBase = smem_u32(sm);
    const uint32_t aEnd  = aBase + NST * TILE_A;
    const uint32_t bBase = aEnd;
    const uint32_t bEnd  = bBase + NST * TILE_BB;

    const int tid  = threadIdx.x;
    const int lane = tid & 31;
    const int wid  = tid >> 5;
    const int wm   = wid >> 1;        // 0..3  (32 rows each)
    const int wn   = wid & 1;         // 0..1  (BNT/2 cols each)
    const int bCol = blockIdx.x * BNT;
    const int bRow = blockIdx.y * BM;

    // A loader: row = tid/2, 4 x 16B chunks (64 B per thread)
    const int rowA = tid >> 1;
    const int cA0  = (tid & 1) * 4;
    const uint32_t stOffA = (uint32_t)(rowA * (LDSR * 2) + cA0 * 16);
    // B loader
    const int rowB = (BNT == 128) ? (tid >> 1) : (tid >> 2);
    const int cB0  = (BNT == 128) ? ((tid & 1) * 4) : ((tid & 3) * 2);
    const uint32_t stOffB = (uint32_t)(rowB * (LDSR * 2) + cB0 * 16);

    const uint32_t lrow = (uint32_t)(lane & 15);
    const uint32_t lcol = (uint32_t)((lane >> 4) * 8);
    const uint32_t aOff0 = ((wm * 32 +  0 + lrow) * LDSR + lcol) * 2;
    const uint32_t aOff1 = ((wm * 32 + 16 + lrow) * LDSR + lcol) * 2;
    uint32_t bOff[G];
    #pragma unroll
    for (int g = 0; g < G; ++g)
        bOff[g] = ((wn * (BNT / 2) + g * 16 + lrow) * LDSR + lcol) * 2;

    auto load_tile = [&](int kt, uint32_t aDst, uint32_t bDst) {
        int kb = kt * BK;
        const uint16_t* aSrc = A + (size_t)(bRow + rowA) * K + kb + cA0 * 8;
        #pragma unroll
        for (int c = 0; c < 4; ++c)
            asm volatile("cp.async.cg.shared.global [%0], [%1], 16;"
                         :: "r"(aDst + stOffA + c * 16), "l"(aSrc + c * 8)
                         : "memory");
        const uint16_t* bSrc = B + (size_t)(bCol + rowB) * K + kb + cB0 * 8;
        #pragma unroll
        for (int c = 0; c < CPB; ++c)
            asm volatile("cp.async.cg.shared.global [%0], [%1], 16;"
                         :: "r"(bDst + stOffB + c * 16), "l"(bSrc + c * 8)
                         : "memory");
    };

    float acc[2][NF][4];
    #pragma unroll
    for (int i = 0; i < 2; ++i)
        #pragma unroll
        for (int j = 0; j < NF; ++j)
            #pragma unroll
            for (int r = 0; r < 4; ++r) acc[i][j][r] = 0.0f;

    // Prologue: fill NST-1 stages
    #pragma unroll
    for (int s = 0; s < NST - 1; ++s) {
        load_tile(s, aBase + s * TILE_A, bBase + s * TILE_BB);
        asm volatile("cp.async.commit_group;" ::: "memory");
    }

    uint32_t rdA = aBase, rdB = bBase;
    uint32_t wrA = aBase + (NST - 1) * TILE_A;
    uint32_t wrB = bBase + (NST - 1) * TILE_BB;

    for (int kt = 0; kt < KT; ++kt) {
        asm volatile("cp.async.wait_group %0;" :: "n"(NST - 2) : "memory");
        __syncthreads();
        if (kt + NST - 1 < KT) load_tile(kt + NST - 1, wrA, wrB);
        asm volatile("cp.async.commit_group;" ::: "memory");
        wrA += TILE_A;  if (wrA == aEnd) wrA = aBase;
        wrB += TILE_BB; if (wrB == bEnd) wrB = bBase;

        // 4 K=16 phases as two proven 2-phase bodies (h = 0,1 at +64h bytes).
        #pragma unroll
        for (int h = 0; h < 2; ++h) {
            const uint32_t o = (uint32_t)(h * 64);
            uint32_t a0[2][4], a1[2][4], b0[G][4], b1[G][4];
            LDSM_X4(a0[0], rdA + aOff0 + o);
            LDSM_X4(a0[1], rdA + aOff1 + o);
            #pragma unroll
            for (int g = 0; g < G; ++g) LDSM_X4(b0[g], rdB + bOff[g] + o);
            LDSM_X4(a1[0], rdA + aOff0 + o + 32);
            LDSM_X4(a1[1], rdA + aOff1 + o + 32);

            #pragma unroll
            for (int mf = 0; mf < 2; ++mf)
                #pragma unroll
                for (int g = 0; g < G; ++g) {
                    MMA_FP16(acc[mf][2 * g],     a0[mf], b0[g][0], b0[g][2]);
                    MMA_FP16(acc[mf][2 * g + 1], a0[mf], b0[g][1], b0[g][3]);
                }

            #pragma unroll
            for (int g = 0; g < G; ++g) LDSM_X4(b1[g], rdB + bOff[g] + o + 32);

            #pragma unroll
            for (int mf = 0; mf < 2; ++mf)
                #pragma unroll
                for (int g = 0; g < G; ++g) {
                    MMA_FP16(acc[mf][2 * g],     a1[mf], b1[g][0], b1[g][2]);
                    MMA_FP16(acc[mf][2 * g + 1], a1[mf], b1[g][1], b1[g][3]);
                }
        }

        rdA += TILE_A;  if (rdA == aEnd) rdA = aBase;
        rdB += TILE_BB; if (rdB == bEnd) rdB = bBase;
    }

    if (MODE == 0) {
        // Fused gate epilogue (row pairing is N-width independent).
        const int q    = lane >> 2;
        const bool odd = (q & 1) != 0;
        const int cB   = bCol + wn * (BNT / 2) + (lane & 3) * 2;
        #pragma unroll
        for (int nf = 0; nf < NF; ++nf) {
            const int c = cB + nf * 8;
            const float2 b2v = *(const float2*)&aux[c];
            #pragma unroll
            for (int mf = 0; mf < 2; ++mf) {
                #pragma unroll
                for (int half = 0; half < 2; ++half) {
                    float x = acc[mf][nf][half * 2 + 0];
                    float y = acc[mf][nf][half * 2 + 1];
                    int fl = ((x + b2v.x) > 0.0f ? 1 : 0) |
                             ((y + b2v.y) > 0.0f ? 2 : 0);
                    int pf = __shfl_xor_sync(0xFFFFFFFFu, fl, 4);
                    if (odd) {
                        int r = bRow + wm * 32 + mf * 16 + half * 8 + q;
                        int tb = r >> 1;
                        float tx = (pf & 1) ? x : 0.0f;
                        float ty = (pf & 2) ? y : 0.0f;
                        __half2 h2;
                        h2.x = __float2half_rn(tx);
                        h2.y = __float2half_rn(ty);
                        *(__half2*)&g_T2h[(size_t)tb * H2 + c] = h2;
                    }
                }
            }
        }
    } else {
        // Fused sum-of-squares epilogue (deterministic).
        float s = 0.0f;
        #pragma unroll
        for (int mf = 0; mf < 2; ++mf)
            #pragma unroll
            for (int nf = 0; nf < NF; ++nf)
                #pragma unroll
                for (int r = 0; r < 4; ++r) {
                    float v = acc[mf][nf][r];
                    s = fmaf(v, v, s);
                }
        #pragma unroll
        for (int o = 16; o > 0; o >>= 1)
            s += __shfl_xor_sync(0xFFFFFFFFu, s, o);
        __syncthreads();
        float* red = (float*)sm;
        if (lane == 0) red[wid] = s;
        __syncthreads();
        if (tid == 0) {
            float tot = 0.0f;
            #pragma unroll
            for (int w = 0; w < 8; ++w) tot += red[w];
            g_part[blockIdx.y * gridDim.x + blockIdx.x] = tot;
        }
    }
}

// ---------------------------------------------------------------------------
// Final deterministic sum over n partials.
// ---------------------------------------------------------------------------
__global__ void k_finalize(float* __restrict__ out, int n) {
    __shared__ float red[256];
    float s = 0.0f;
    for (int i = threadIdx.x; i < n; i += 256) s += g_part[i];
    red[threadIdx.x] = s;
    __syncthreads();
    for (int o = 128; o > 0; o >>= 1) {
        if (threadIdx.x < o) red[threadIdx.x] += red[threadIdx.x + o];
        __syncthreads();
    }
    if (threadIdx.x == 0) out[0] = red[0];
}

// ---------------------------------------------------------------------------
// Launch.  Inputs: 0:c0 1:c1 2:interior 3:W1 4:b1 5:W2 6:b2 7:W3 8:b3(unused)
// ---------------------------------------------------------------------------
#define SMEM_M0 (3 * (TILE_A + 128 * LDSR * 2))   // 110592: 3 stages, 2 CTAs/SM
#define SMEM_M1 (4 * (TILE_A + 64 * LDSR * 2))    // 110592: 4 stages, 2 CTAs/SM

extern "C" void kernel_launch(void* const* d_in, const int* in_sizes, int n_in,
                              void* d_out, int out_size) {
    const float* c0       = (const float*)d_in[0];
    const float* c1       = (const float*)d_in[1];
    const float* interior = (const float*)d_in[2];
    const float* W1       = (const float*)d_in[3];
    const float* b1       = (const float*)d_in[4];
    const float* W2       = (const float*)d_in[5];
    const float* b2       = (const float*)d_in[6];
    const float* W3       = (const float*)d_in[7];
    (void)in_sizes; (void)n_in; (void)out_size;

    __half *X1h, *W2th, *W3th, *T2h;
    cudaGetSymbolAddress((void**)&X1h,  g_X1h);
    cudaGetSymbolAddress((void**)&W2th, g_W2th);
    cudaGetSymbolAddress((void**)&W3th, g_W3th);
    cudaGetSymbolAddress((void**)&T2h,  g_T2h);

    cudaFuncSetAttribute((const void*)k_mma_gemm<0, 128, 3>,
                         cudaFuncAttributeMaxDynamicSharedMemorySize, SMEM_M0);
    cudaFuncSetAttribute((const void*)k_mma_gemm<1, 64, 4>,
                         cudaFuncAttributeMaxDynamicSharedMemorySize, SMEM_M1);

    // Weight prep: W2, W3 -> transposed fp16 (half2-coalesced writes)
    k_transpose_half<<<dim3(H2 / 32, H1 / 64), dim3(32, 8)>>>(W2, W2th, H1, H2);
    k_transpose_half<<<dim3(DD / 32, H2 / 64), dim3(32, 8)>>>(W3, W3th, H2, DD);

    // L1 forward + tangent (interleaved fp16 rows, pads zeroed in-kernel)
    k_layer1<<<1024, 256>>>(c0, c1, interior, W1, b1);

    // GEMM1 (fp16, BK=64, 3 stages) + fused gate
    k_mma_gemm<0, 128, 3><<<dim3(H2 / 128, X1_ROWS / BM), 256, SMEM_M0>>>(
        (const uint16_t*)X1h, (const uint16_t*)W2th, b2, H1, H1 / BK);

    // GEMM2 (fp16, BK=64, 4 stages, 128x64 tiles) + fused sqsum
    const int g2x = DD / 64, g2y = T2_ROWS / BM;   // 48 x 8 = 384
    k_mma_gemm<1, 64, 4><<<dim3(g2x, g2y), 256, SMEM_M1>>>(
        (const uint16_t*)T2h, (const uint16_t*)W3th, nullptr, H2, H2 / BK);

    // energy = sum of partials (fixed order)
    k_finalize<<<1, 256>>>((float*)d_out, g2x * g2y);
}

// round 16
// speedup vs baseline: 1.2038x; 1.2038x over previous
#include <cuda_runtime.h>
#include <cuda_fp16.h>
#include <cstdint>

// Problem constants
#define MM   32
#define BB   1000
#define H1   512
#define H2   2048
#define DD   3072

#define X1_ROWS 2048   // interleaved: row 2b = h_b, row 2b+1 = t_b (b<1024, pads 0)
#define T2_ROWS 1024
#define NPART   512

// ---------------------------------------------------------------------------
// Static device scratch (all fp16).
// ---------------------------------------------------------------------------
__device__ __align__(16) __half g_X1h[X1_ROWS * H1];    // 2 MB
__device__ __align__(16) __half g_W2th[H2 * H1];        // [N=2048,K=512]  2 MB
__device__ __align__(16) __half g_W3th[DD * H2];        // [N=3072,K=2048] 12 MB
__device__ __align__(16) __half g_T2h[T2_ROWS * H2];    // 4 MB
__device__ float g_part[NPART];

__device__ __forceinline__ uint32_t smem_u32(const void* p) {
    uint32_t a;
    asm("{ .reg .u64 t; cvta.to.shared.u64 t, %1; cvt.u32.u64 %0, t; }"
        : "=r"(a) : "l"(p));
    return a;
}

// ---------------------------------------------------------------------------
// K1: layer-1 forward + tangent -> interleaved fp16 rows (2b = h, 2b+1 = t).
// ---------------------------------------------------------------------------
__global__ void k_layer1(const float* __restrict__ c0,
                         const float* __restrict__ c1,
                         const float* __restrict__ interior,
                         const float* __restrict__ W1,
                         const float* __restrict__ b1) {
    int b = blockIdx.x;            // 0..1023
    if (b >= BB) {
        const __half z = __float2half(0.0f);
        for (int k = threadIdx.x; k < H1; k += blockDim.x) {
            g_X1h[(2 * b) * H1 + k]     = z;
            g_X1h[(2 * b + 1) * H1 + k] = z;
        }
        return;
    }
    __shared__ float zs[MM], ds[MM];
    if (threadIdx.x < MM) {
        int m = threadIdx.x;
        float zb = (b == 0)    ? c0[m] : interior[(b - 1) * MM + m];
        float cn = (b == BB-1) ? c1[m] : interior[b * MM + m];
        zs[m] = zb;
        ds[m] = cn - zb;
    }
    __syncthreads();
    for (int k = threadIdx.x; k < H1; k += blockDim.x) {
        float a = b1[k];
        float g = 0.0f;
        #pragma unroll
        for (int m = 0; m < MM; ++m) {
            float w = W1[m * H1 + k];
            a = fmaf(zs[m], w, a);
            g = fmaf(ds[m], w, g);
        }
        float h = fmaxf(a, 0.0f);
        float t = (a > 0.0f) ? g : 0.0f;
        g_X1h[(2 * b) * H1 + k]     = __float2half_rn(h);
        g_X1h[(2 * b + 1) * H1 + k] = __float2half_rn(t);
    }
}

// ---------------------------------------------------------------------------
// Transpose -> fp16:  W[K,N] fp32 -> T[N,K] fp16.  64-wide K tiles, half2
// stores (128 B/warp coalesced writes).  Requires K%64==0, N%32==0.
// ---------------------------------------------------------------------------
__global__ void k_transpose_half(const float* __restrict__ W,
                                 __half* __restrict__ T,
                                 int K, int N) {
    __shared__ float tile[64][33];
    int n0 = blockIdx.x * 32;
    int k0 = blockIdx.y * 64;
    int tx = threadIdx.x, ty = threadIdx.y;   // (32, 8)
    #pragma unroll
    for (int r = ty; r < 64; r += 8)
        tile[r][tx] = W[(size_t)(k0 + r) * N + n0 + tx];
    __syncthreads();
    #pragma unroll
    for (int n = ty; n < 32; n += 8) {
        __half2 v = __halves2half2(__float2half_rn(tile[2 * tx][n]),
                                   __float2half_rn(tile[2 * tx + 1][n]));
        *(__half2*)&T[(size_t)(n0 + n) * K + k0 + 2 * tx] = v;
    }
}

// ---------------------------------------------------------------------------
// Single-pass fp16 mma.sync GEMM, BK=32, multi-stage cp.async (R14 config —
// the best measured; R15's BK=64 variant regressed and was reverted).
// Template: MODE 0 = gate epilogue; MODE 1 = sqsum epilogue.
//           BNT = N tile width; NST = pipeline stages; MINB = min blocks/SM.
// CTA tile 128 x BNT, 8 warps, warp tile 32 x (BNT/2).
// ---------------------------------------------------------------------------
#define BM 128
#define BK 32
#define LDSR 40                     // 16-bit elems/row (80 B) -> conflict-free ldmatrix
#define TILE_A (BM * LDSR * 2)      // 10240 bytes per A stage

#define LDSM_X4(d, addr)                                                     \
    asm volatile("ldmatrix.sync.aligned.m8n8.x4.shared.b16 {%0,%1,%2,%3}, [%4];" \
                 : "=r"((d)[0]), "=r"((d)[1]), "=r"((d)[2]), "=r"((d)[3])    \
                 : "r"(addr))

#define MMA_FP16(ac, av, r0, r1)                                             \
    asm volatile(                                                            \
        "mma.sync.aligned.m16n8k16.row.col.f32.f16.f16.f32 "                 \
        "{%0,%1,%2,%3}, {%4,%5,%6,%7}, {%8,%9}, {%0,%1,%2,%3};"              \
        : "+f"((ac)[0]), "+f"((ac)[1]), "+f"((ac)[2]), "+f"((ac)[3])         \
        : "r"((av)[0]), "r"((av)[1]), "r"((av)[2]), "r"((av)[3]),            \
          "r"(r0), "r"(r1))

template <int MODE, int BNT, int NST, int MINB>
__global__ void __launch_bounds__(256, MINB)
k_mma_gemm(const uint16_t* __restrict__ A, const uint16_t* __restrict__ B,
           const float* __restrict__ aux,   // MODE0: b2;  MODE1: unused
           int K, int KT) {                 // KT = K/BK
    constexpr int TILE_BB = BNT * LDSR * 2;       // B stage bytes
    constexpr int G  = BNT / 32;                  // ldsm.x4 B groups per warp
    constexpr int NF = BNT / 16;                  // n8 acc frags per warp

    extern __shared__ char sm[];
    const uint32_t aBase = smem_u32(sm);
    const uint32_t aEnd  = aBase + NST * TILE_A;
    const uint32_t bBase = aEnd;
    const uint32_t bEnd  = bBase + NST * TILE_BB;

    const int tid  = threadIdx.x;
    const int lane = tid & 31;
    const int wid  = tid >> 5;
    const int wm   = wid >> 1;        // 0..3  (32 rows each)
    const int wn   = wid & 1;         // 0..1  (BNT/2 cols each)
    const int bCol = blockIdx.x * BNT;
    const int bRow = blockIdx.y * BM;

    // A loader: row = tid/2, two 16B chunks
    const int rowA = tid >> 1;
    const int cA0  = (tid & 1) * 2;
    const uint32_t stOffA = (uint32_t)(rowA * (LDSR * 2) + cA0 * 16);
    // B loader
    const int rowB = (BNT == 128) ? (tid >> 1) : (tid >> 2);
    const int cB0  = (BNT == 128) ? ((tid & 1) * 2) : (tid & 3);
    const uint32_t stOffB = (uint32_t)(rowB * (LDSR * 2) + cB0 * 16);

    const uint32_t lrow = (uint32_t)(lane & 15);
    const uint32_t lcol = (uint32_t)((lane >> 4) * 8);
    const uint32_t aOff0 = ((wm * 32 +  0 + lrow) * LDSR + lcol) * 2;
    const uint32_t aOff1 = ((wm * 32 + 16 + lrow) * LDSR + lcol) * 2;
    uint32_t bOff[G];
    #pragma unroll
    for (int g = 0; g < G; ++g)
        bOff[g] = ((wn * (BNT / 2) + g * 16 + lrow) * LDSR + lcol) * 2;

    auto load_tile = [&](int kt, uint32_t aDst, uint32_t bDst) {
        int kb = kt * BK;
        const uint16_t* aSrc = A + (size_t)(bRow + rowA) * K + kb + cA0 * 8;
        asm volatile("cp.async.cg.shared.global [%0], [%1], 16;"
                     :: "r"(aDst + stOffA), "l"(aSrc) : "memory");
        asm volatile("cp.async.cg.shared.global [%0], [%1], 16;"
                     :: "r"(aDst + stOffA + 16), "l"(aSrc + 8) : "memory");
        const uint16_t* bSrc = B + (size_t)(bCol + rowB) * K + kb + cB0 * 8;
        asm volatile("cp.async.cg.shared.global [%0], [%1], 16;"
                     :: "r"(bDst + stOffB), "l"(bSrc) : "memory");
        if (BNT == 128) {
            asm volatile("cp.async.cg.shared.global [%0], [%1], 16;"
                         :: "r"(bDst + stOffB + 16), "l"(bSrc + 8) : "memory");
        }
    };

    float acc[2][NF][4];
    #pragma unroll
    for (int i = 0; i < 2; ++i)
        #pragma unroll
        for (int j = 0; j < NF; ++j)
            #pragma unroll
            for (int r = 0; r < 4; ++r) acc[i][j][r] = 0.0f;

    // Prologue: fill NST-1 stages
    #pragma unroll
    for (int s = 0; s < NST - 1; ++s) {
        load_tile(s, aBase + s * TILE_A, bBase + s * TILE_BB);
        asm volatile("cp.async.commit_group;" ::: "memory");
    }

    uint32_t rdA = aBase, rdB = bBase;
    uint32_t wrA = aBase + (NST - 1) * TILE_A;
    uint32_t wrB = bBase + (NST - 1) * TILE_BB;

    for (int kt = 0; kt < KT; ++kt) {
        asm volatile("cp.async.wait_group %0;" :: "n"(NST - 2) : "memory");
        __syncthreads();
        if (kt + NST - 1 < KT) load_tile(kt + NST - 1, wrA, wrB);
        asm volatile("cp.async.commit_group;" ::: "memory");
        wrA += TILE_A;  if (wrA == aEnd) wrA = aBase;
        wrB += TILE_BB; if (wrB == bEnd) wrB = bBase;

        uint32_t a0[2][4], a1[2][4], b0[G][4], b1[G][4];
        LDSM_X4(a0[0], rdA + aOff0);
        LDSM_X4(a0[1], rdA + aOff1);
        #pragma unroll
        for (int g = 0; g < G; ++g) LDSM_X4(b0[g], rdB + bOff[g]);
        LDSM_X4(a1[0], rdA + aOff0 + 32);
        LDSM_X4(a1[1], rdA + aOff1 + 32);

        #pragma unroll
        for (int mf = 0; mf < 2; ++mf)
            #pragma unroll
            for (int g = 0; g < G; ++g) {
                MMA_FP16(acc[mf][2 * g],     a0[mf], b0[g][0], b0[g][2]);
                MMA_FP16(acc[mf][2 * g + 1], a0[mf], b0[g][1], b0[g][3]);
            }

        #pragma unroll
        for (int g = 0; g < G; ++g) LDSM_X4(b1[g], rdB + bOff[g] + 32);

        #pragma unroll
        for (int mf = 0; mf < 2; ++mf)
            #pragma unroll
            for (int g = 0; g < G; ++g) {
                MMA_FP16(acc[mf][2 * g],     a1[mf], b1[g][0], b1[g][2]);
                MMA_FP16(acc[mf][2 * g + 1], a1[mf], b1[g][1], b1[g][3]);
            }

        rdA += TILE_A;  if (rdA == aEnd) rdA = aBase;
        rdB += TILE_BB; if (rdB == bEnd) rdB = bBase;
    }

    if (MODE == 0) {
        // Fused gate epilogue (row pairing is N-width independent).
        const int q    = lane >> 2;
        const bool odd = (q & 1) != 0;
        const int cB   = bCol + wn * (BNT / 2) + (lane & 3) * 2;
        #pragma unroll
        for (int nf = 0; nf < NF; ++nf) {
            const int c = cB + nf * 8;
            const float2 b2v = *(const float2*)&aux[c];
            #pragma unroll
            for (int mf = 0; mf < 2; ++mf) {
                #pragma unroll
                for (int half = 0; half < 2; ++half) {
                    float x = acc[mf][nf][half * 2 + 0];
                    float y = acc[mf][nf][half * 2 + 1];
                    int fl = ((x + b2v.x) > 0.0f ? 1 : 0) |
                             ((y + b2v.y) > 0.0f ? 2 : 0);
                    int pf = __shfl_xor_sync(0xFFFFFFFFu, fl, 4);
                    if (odd) {
                        int r = bRow + wm * 32 + mf * 16 + half * 8 + q;
                        int tb = r >> 1;
                        float tx = (pf & 1) ? x : 0.0f;
                        float ty = (pf & 2) ? y : 0.0f;
                        __half2 h2;
                        h2.x = __float2half_rn(tx);
                        h2.y = __float2half_rn(ty);
                        *(__half2*)&g_T2h[(size_t)tb * H2 + c] = h2;
                    }
                }
            }
        }
    } else {
        // Fused sum-of-squares epilogue (deterministic).
        float s = 0.0f;
        #pragma unroll
        for (int mf = 0; mf < 2; ++mf)
            #pragma unroll
            for (int nf = 0; nf < NF; ++nf)
                #pragma unroll
                for (int r = 0; r < 4; ++r) {
                    float v = acc[mf][nf][r];
                    s = fmaf(v, v, s);
                }
        #pragma unroll
        for (int o = 16; o > 0; o >>= 1)
            s += __shfl_xor_sync(0xFFFFFFFFu, s, o);
        __syncthreads();
        float* red = (float*)sm;
        if (lane == 0) red[wid] = s;
        __syncthreads();
        if (tid == 0) {
            float tot = 0.0f;
            #pragma unroll
            for (int w = 0; w < 8; ++w) tot += red[w];
            g_part[blockIdx.y * gridDim.x + blockIdx.x] = tot;
        }
    }
}

// ---------------------------------------------------------------------------
// Final deterministic sum over n partials.
// ---------------------------------------------------------------------------
__global__ void k_finalize(float* __restrict__ out, int n) {
    __shared__ float red[256];
    float s = 0.0f;
    for (int i = threadIdx.x; i < n; i += 256) s += g_part[i];
    red[threadIdx.x] = s;
    __syncthreads();
    for (int o = 128; o > 0; o >>= 1) {
        if (threadIdx.x < o) red[threadIdx.x] += red[threadIdx.x + o];
        __syncthreads();
    }
    if (threadIdx.x == 0) out[0] = red[0];
}

// ---------------------------------------------------------------------------
// Launch.  Inputs: 0:c0 1:c1 2:interior 3:W1 4:b1 5:W2 6:b2 7:W3 8:b3(unused)
// ---------------------------------------------------------------------------
#define SMEM_M0 (5 * (TILE_A + 128 * LDSR * 2))   // 102400, 5 stages, 2 CTAs/SM
#define SMEM_M1 (4 * (TILE_A + 64 * LDSR * 2))    // 61440,  4 stages, 3 CTAs/SM

extern "C" void kernel_launch(void* const* d_in, const int* in_sizes, int n_in,
                              void* d_out, int out_size) {
    const float* c0       = (const float*)d_in[0];
    const float* c1       = (const float*)d_in[1];
    const float* interior = (const float*)d_in[2];
    const float* W1       = (const float*)d_in[3];
    const float* b1       = (const float*)d_in[4];
    const float* W2       = (const float*)d_in[5];
    const float* b2       = (const float*)d_in[6];
    const float* W3       = (const float*)d_in[7];
    (void)in_sizes; (void)n_in; (void)out_size;

    __half *X1h, *W2th, *W3th, *T2h;
    cudaGetSymbolAddress((void**)&X1h,  g_X1h);
    cudaGetSymbolAddress((void**)&W2th, g_W2th);
    cudaGetSymbolAddress((void**)&W3th, g_W3th);
    cudaGetSymbolAddress((void**)&T2h,  g_T2h);

    cudaFuncSetAttribute((const void*)k_mma_gemm<0, 128, 5, 2>,
                         cudaFuncAttributeMaxDynamicSharedMemorySize, SMEM_M0);
    cudaFuncSetAttribute((const void*)k_mma_gemm<1, 64, 4, 3>,
                         cudaFuncAttributeMaxDynamicSharedMemorySize, SMEM_M1);

    // Weight prep: W2, W3 -> transposed fp16 (half2-coalesced writes)
    k_transpose_half<<<dim3(H2 / 32, H1 / 64), dim3(32, 8)>>>(W2, W2th, H1, H2);
    k_transpose_half<<<dim3(DD / 32, H2 / 64), dim3(32, 8)>>>(W3, W3th, H2, DD);

    // L1 forward + tangent (interleaved fp16 rows, pads zeroed in-kernel)
    k_layer1<<<1024, 256>>>(c0, c1, interior, W1, b1);

    // GEMM1 (fp16, R14 config: BK=32, 5 stages) + fused gate
    k_mma_gemm<0, 128, 5, 2><<<dim3(H2 / 128, X1_ROWS / BM), 256, SMEM_M0>>>(
        (const uint16_t*)X1h, (const uint16_t*)W2th, b2, H1, H1 / BK);

    // GEMM2 (fp16, R14 config: BK=32, 4 stages, 3 CTAs/SM) + fused sqsum
    const int g2x = DD / 64, g2y = T2_ROWS / BM;   // 48 x 8 = 384
    k_mma_gemm<1, 64, 4, 3><<<dim3(g2x, g2y), 256, SMEM_M1>>>(
        (const uint16_t*)T2h, (const uint16_t*)W3th, nullptr, H2, H2 / BK);

    // energy = sum of partials (fixed order)
    k_finalize<<<1, 256>>>((float*)d_out, g2x * g2y);
}